// round 2
// baseline (speedup 1.0000x reference)
#include <cuda_runtime.h>
#include <cstdint>
#include <cstddef>

// Problem constants
#define NSAMP   4096
#define IDIM    512
#define HDIM    128
#define LSTRIDE (HDIM + HDIM*HDIM)   // 16512 rows of W per layer
#define NLAYER  3

// Tiling
#define NB      32                   // samples per CTA
#define KC      64                   // K-chunk staged in smem
#define NSTAGE  (IDIM/KC)            // 8
#define XPITCH  516                  // int_x smem pitch (floats): bank-spread + 16B rows
#define HPITCH  132                  // h smem pitch
#define BPITCH  68                   // W-chunk smem pitch (floats)
#define THREADS 128

#define SMEM_FLOATS (NB*XPITCH + NB*HPITCH + 2*HDIM*BPITCH)
#define SMEM_BYTES  (SMEM_FLOATS*4)

// Packed dual-fp32 FMA (Blackwell): d = a*b + d componentwise on f32 pairs.
__device__ __forceinline__ void fma2(unsigned long long &c, unsigned long long a,
                                     unsigned long long b) {
    asm("fma.rn.f32x2 %0, %1, %2, %0;" : "+l"(c) : "l"(a), "l"(b));
}

__device__ __forceinline__ void cp16(float* s, const float* g) {
    unsigned sa = (unsigned)__cvta_generic_to_shared(s);
    asm volatile("cp.async.cg.shared.global [%0], [%1], 16;" :: "r"(sa), "l"(g));
}
__device__ __forceinline__ void cp_commit() { asm volatile("cp.async.commit_group;"); }
__device__ __forceinline__ void cp_wait0()  { asm volatile("cp.async.wait_group 0;"); }

// Fully fused InteractionNet: each CTA owns NB samples end-to-end across all 3
// layers. Per layer, loop over 129 "chunks" (p = 0..127 weight chunks + 1 bias
// chunk). Each chunk is a C[NB x 128] = int_x[NB x 512] @ Wrows[128 x 512]^T
// GEMM done with f32x2 packed FMAs (accumulating k-even/k-odd partial sums in
// the two f32 lanes), then folded into the next-layer activation:
//   h_next[n,q] += (dot + b[row]) * (chunk<128 ? h[n,p=chunk] : 1).
__global__ void __launch_bounds__(THREADS, 1)
inet_kernel(const float* __restrict__ gx_int, const float* __restrict__ gx,
            const float* __restrict__ gW, const float* __restrict__ gb,
            float* __restrict__ gout)
{
    extern __shared__ float smem[];
    float* xs = smem;                       // [NB][XPITCH]  int_x tile (resident)
    float* hs = xs + NB*XPITCH;             // [NB][HPITCH]  current activation
    float* Bs = hs + NB*HPITCH;             // [2][HDIM][BPITCH] W-chunk stages

    const int tid = threadIdx.x;
    const int n0  = blockIdx.x * NB;
    const int tqg = tid & 15;               // q-group: q = tqg + 16*j, j=0..7
    const int tng = tid >> 4;               // n-group: n = tng*4 + i, i=0..3

    // Stage the per-CTA int_x tile (NB x 512) and initial h = x (NB x 128).
    for (int i = tid; i < NB*(IDIM/4); i += THREADS) {
        int n  = i >> 7;                    // / (IDIM/4)
        int k4 = i & 127;
        cp16(&xs[n*XPITCH + k4*4], &gx_int[(size_t)(n0+n)*IDIM + (size_t)k4*4]);
    }
    for (int i = tid; i < NB*(HDIM/4); i += THREADS) {
        int n  = i >> 5;
        int q4 = i & 31;
        cp16(&hs[n*HPITCH + q4*4], &gx[(size_t)(n0+n)*HDIM + (size_t)q4*4]);
    }
    cp_commit(); cp_wait0();
    __syncthreads();

    for (int layer = 0; layer < NLAYER; ++layer) {
        const int base = layer * LSTRIDE;

        float hn[4][8];
        #pragma unroll
        for (int i = 0; i < 4; ++i)
            #pragma unroll
            for (int j = 0; j < 8; ++j) hn[i][j] = 0.f;

        for (int c = 0; c <= HDIM; ++c) {
            // c < 128: weight chunk p=c -> rows base+128+c*128+q, multiplier h[n,c]
            // c == 128: bias chunk     -> rows base+q,            multiplier 1
            const int rowbase = base + (c < HDIM ? HDIM + c*HDIM : 0);
            const float* wrow = gW + (size_t)(rowbase + tid) * IDIM; // this thread stages row q=tid

            unsigned long long acc[4][8];
            #pragma unroll
            for (int i = 0; i < 4; ++i)
                #pragma unroll
                for (int j = 0; j < 8; ++j) acc[i][j] = 0ull;

            // Preload stage 0 into buffer 0.
            #pragma unroll
            for (int v = 0; v < KC/4; ++v)
                cp16(&Bs[tid*BPITCH + v*4], wrow + v*4);
            cp_commit();

            int buf = 0;
            for (int s = 0; s < NSTAGE; ++s) {
                cp_wait0();
                __syncthreads();            // stage s visible; everyone done with buf^1
                if (s + 1 < NSTAGE) {       // prefetch stage s+1 into the other buffer
                    const float* src = wrow + (s+1)*KC;
                    float* dst = &Bs[(buf^1)*HDIM*BPITCH + tid*BPITCH];
                    #pragma unroll
                    for (int v = 0; v < KC/4; ++v)
                        cp16(dst + v*4, src + v*4);
                    cp_commit();
                }
                // Compute: k-pairs, two fp32 lanes accumulate k-even/k-odd sums.
                const float* bb = &Bs[buf*HDIM*BPITCH];
                const int kbase = s*KC;
                #pragma unroll 8
                for (int kk = 0; kk < KC; kk += 2) {
                    unsigned long long av[4], bv[8];
                    #pragma unroll
                    for (int i = 0; i < 4; ++i)
                        av[i] = *reinterpret_cast<const unsigned long long*>(
                                    &xs[(tng*4+i)*XPITCH + kbase + kk]);
                    #pragma unroll
                    for (int j = 0; j < 8; ++j)
                        bv[j] = *reinterpret_cast<const unsigned long long*>(
                                    &bb[(tqg + 16*j)*BPITCH + kk]);
                    #pragma unroll
                    for (int i = 0; i < 4; ++i)
                        #pragma unroll
                        for (int j = 0; j < 8; ++j)
                            fma2(acc[i][j], av[i], bv[j]);
                }
                buf ^= 1;
            }

            // Fold chunk into h_next.
            float m[4];
            #pragma unroll
            for (int i = 0; i < 4; ++i)
                m[i] = (c < HDIM) ? hs[(tng*4+i)*HPITCH + c] : 1.0f;
            #pragma unroll
            for (int j = 0; j < 8; ++j) {
                const int q = tqg + 16*j;
                const float brow = __ldg(&gb[rowbase + q]);
                #pragma unroll
                for (int i = 0; i < 4; ++i) {
                    union { unsigned long long u; float2 f; } cv;
                    cv.u = acc[i][j];
                    hn[i][j] += (cv.f.x + cv.f.y + brow) * m[i];
                }
            }
        }

        __syncthreads();
        if (layer < NLAYER-1) {
            #pragma unroll
            for (int i = 0; i < 4; ++i)
                #pragma unroll
                for (int j = 0; j < 8; ++j) {
                    float v = hn[i][j];
                    hs[(tng*4+i)*HPITCH + tqg + 16*j] = v > 0.f ? v : 0.f; // relu
                }
            __syncthreads();
        } else {
            #pragma unroll
            for (int i = 0; i < 4; ++i)
                #pragma unroll
                for (int j = 0; j < 8; ++j)
                    gout[(size_t)(n0 + tng*4 + i)*HDIM + tqg + 16*j] = hn[i][j];
        }
    }
}

extern "C" void kernel_launch(void* const* d_in, const int* in_sizes, int n_in,
                              void* d_out, int out_size)
{
    // Identify inputs by element count (robust to metadata order):
    // int_x: 4096*512, x: 4096*128, W: 49536*512, b: 49536
    const float *int_x = nullptr, *x = nullptr, *W = nullptr, *b = nullptr;
    for (int i = 0; i < n_in; ++i) {
        const int sz = in_sizes[i];
        if      (sz == NSAMP*IDIM)              int_x = (const float*)d_in[i];
        else if (sz == NSAMP*HDIM)              x     = (const float*)d_in[i];
        else if (sz == NLAYER*LSTRIDE*IDIM)     W     = (const float*)d_in[i];
        else if (sz == NLAYER*LSTRIDE)          b     = (const float*)d_in[i];
    }

    cudaFuncSetAttribute(inet_kernel, cudaFuncAttributeMaxDynamicSharedMemorySize,
                         SMEM_BYTES);
    inet_kernel<<<NSAMP/NB, THREADS, SMEM_BYTES>>>(int_x, x, W, b, (float*)d_out);
}